// round 4
// baseline (speedup 1.0000x reference)
#include <cuda_runtime.h>

// TimeSeriesWineSNN: 3-layer LIF SNN, T sequential steps, B=4096.
// I=8 -> H1=28 -> H2=8 -> O=4. beta=0.9, thr=1.0 (subtract reset).
// Outputs: mem3, spk3, spk1, spk2, each [T,B,C].
//
// 8 lanes cooperate per batch element (32768 threads). Spikes exchanged
// intra-octet via __shfl_sync(width=8).
//
// NUMERICS hypothesis (XLA GPU, dots NOT sent to cuBLAS):
//  dot -> multiply + warp-shuffle-tree reduce:
//   * each product rounded separately: p_k = rn(x_k*w_k)  (NO fma)
//   * width-8 rows:  ((p0+p4)+(p2+p6)) + ((p1+p5)+(p3+p7))
//   * width-28 row: 32-lane tree with zero padding (exact), implemented below
//  LIF epilogue fusion with LLVM contraction:
//   m = fma(beta, m_prev, cur + b) - s_prev ;  s = (m > 1) ? 1 : 0
//  reset_t == spk_{t-1} (reuse stored spike float, bit-exact).

constexpr int   Bb  = 4096;
constexpr int   Ii  = 8;
constexpr int   H1  = 28;
constexpr int   H2  = 8;
constexpr int   Oo  = 4;
constexpr float BETA = 0.9f;
constexpr float THR  = 1.0f;

// tree-sum of 8 individually-rounded products (lane-0 result of an
// 8-lane shfl reduction; identical for down/xor variants & zero padding)
__device__ __forceinline__ float tree8(const float* __restrict__ p) {
    float a = __fadd_rn(__fadd_rn(p[0], p[4]), __fadd_rn(p[2], p[6]));
    float b = __fadd_rn(__fadd_rn(p[1], p[5]), __fadd_rn(p[3], p[7]));
    return __fadd_rn(a, b);
}

// 32-lane shfl-tree over p[0..27] with p[28..31]=0 (zero adds are exact):
//  q_i  = p_i + p_{i+16}            (i=0..11),  q_i = p_i (i=12..15)
//  r_i  = q_i + q_{i+8}             (i=0..7)
//  s_i  = r_i + r_{i+4}             (i=0..3)
//  tot  = (s_0 + s_2) + (s_1 + s_3)
__device__ __forceinline__ float tree28(const float* __restrict__ p) {
    float r[8];
    #pragma unroll
    for (int i = 0; i < 4; ++i)      // q_{i+8} = p_{i+8}+p_{i+24}
        r[i] = __fadd_rn(__fadd_rn(p[i], p[i + 16]),
                         __fadd_rn(p[i + 8], p[i + 24]));
    #pragma unroll
    for (int i = 4; i < 8; ++i)      // q_{i+8} = p_{i+8}
        r[i] = __fadd_rn(__fadd_rn(p[i], p[i + 16]), p[i + 8]);
    float s0 = __fadd_rn(r[0], r[4]);
    float s1 = __fadd_rn(r[1], r[5]);
    float s2 = __fadd_rn(r[2], r[6]);
    float s3 = __fadd_rn(r[3], r[7]);
    return __fadd_rn(__fadd_rn(s0, s2), __fadd_rn(s1, s3));
}

__global__ void __launch_bounds__(64)
snn_kernel(const float* __restrict__ x,
           const float* __restrict__ W1, const float* __restrict__ b1,
           const float* __restrict__ W2, const float* __restrict__ b2,
           const float* __restrict__ W3, const float* __restrict__ b3,
           float* __restrict__ out_mem3, float* __restrict__ out_spk3,
           float* __restrict__ out_spk1, float* __restrict__ out_spk2,
           int T)
{
    const int tid  = blockIdx.x * blockDim.x + threadIdx.x;
    const int lane = tid & 7;
    const int b    = tid >> 3;
    if (b >= Bb) return;

    // ---- weights into registers (padded layer-1 channels get w=0,b=0) ----
    float w1[4][8], b1r[4];
    #pragma unroll
    for (int p = 0; p < 4; ++p) {
        const int c = 4 * lane + p;
        const bool real = (c < H1);
        b1r[p] = real ? b1[c] : 0.0f;
        #pragma unroll
        for (int k = 0; k < Ii; ++k)
            w1[p][k] = real ? W1[c * Ii + k] : 0.0f;
    }
    float w2[H1], b2r;
    {
        const int c = lane;
        b2r = b2[c];
        #pragma unroll
        for (int k = 0; k < H1; ++k) w2[k] = W2[c * H1 + k];
    }
    float w3[H2], b3r;
    {
        const int c = (lane < Oo) ? lane : 0;
        b3r = b3[c];
        #pragma unroll
        for (int k = 0; k < H2; ++k) w3[k] = W3[c * H2 + k];
    }

    // ---- state ----
    float m1[4] = {0.f, 0.f, 0.f, 0.f};
    float s1f[4] = {0.f, 0.f, 0.f, 0.f};
    float m2 = 0.f, s2f = 0.f, m3 = 0.f, s3f = 0.f;

    // ---- pointers ----
    const size_t sX  = (size_t)Bb * Ii;
    const size_t st1 = (size_t)Bb * H1;
    const size_t st2 = (size_t)Bb * H2;
    const size_t st3 = (size_t)Bb * Oo;

    const float* px = x + (size_t)b * Ii;
    float* p1 = out_spk1 + (size_t)b * H1 + 4 * lane;   // 16B aligned
    float* p2 = out_spk2 + (size_t)b * H2 + lane;
    float* p3 = out_spk3 + (size_t)b * Oo + lane;
    float* pm = out_mem3 + (size_t)b * Oo + lane;

    float4 xa = *(const float4*)px;
    float4 xb = *(const float4*)(px + 4);

    for (int t = 0; t < T; ++t) {
        const float* pn = px + ((t + 1 < T) ? sX : 0);
        const float4 nxa = *(const float4*)pn;
        const float4 nxb = *(const float4*)(pn + 4);
        px = pn;

        const float xk[8] = {xa.x, xa.y, xa.z, xa.w, xb.x, xb.y, xb.z, xb.w};

        // ---------- layer 1 : products rounded separately, tree sum ----------
        #pragma unroll
        for (int p = 0; p < 4; ++p) {
            float pr[8];
            #pragma unroll
            for (int k = 0; k < Ii; ++k) pr[k] = __fmul_rn(xk[k], w1[p][k]);
            float a = __fadd_rn(tree8(pr), b1r[p]);        // bias after dot
            m1[p]  = __fsub_rn(__fmaf_rn(BETA, m1[p], a), s1f[p]);
            s1f[p] = (m1[p] > THR) ? 1.0f : 0.0f;
        }
        if (lane < 7)
            *(float4*)p1 = make_float4(s1f[0], s1f[1], s1f[2], s1f[3]);

        // ---------- all-gather s1 (28 channels) ----------
        float sg[H1];
        #pragma unroll
        for (int src = 0; src < 7; ++src) {
            #pragma unroll
            for (int p = 0; p < 4; ++p)
                sg[4 * src + p] = __shfl_sync(0xffffffffu, s1f[p], src, 8);
        }

        // ---------- layer 2 : 28-wide tree ----------
        {
            float pr[H1];
            #pragma unroll
            for (int k = 0; k < H1; ++k) pr[k] = __fmul_rn(sg[k], w2[k]);
            float a = __fadd_rn(tree28(pr), b2r);
            m2  = __fsub_rn(__fmaf_rn(BETA, m2, a), s2f);
            s2f = (m2 > THR) ? 1.0f : 0.0f;
        }
        *p2 = s2f;

        // ---------- all-gather s2 (8 channels) ----------
        float t2[H2];
        #pragma unroll
        for (int src = 0; src < 8; ++src)
            t2[src] = __shfl_sync(0xffffffffu, s2f, src, 8);

        // ---------- layer 3 : 8-wide tree ----------
        {
            float pr[H2];
            #pragma unroll
            for (int k = 0; k < H2; ++k) pr[k] = __fmul_rn(t2[k], w3[k]);
            float a = __fadd_rn(tree8(pr), b3r);
            m3  = __fsub_rn(__fmaf_rn(BETA, m3, a), s3f);
            s3f = (m3 > THR) ? 1.0f : 0.0f;
        }
        if (lane < Oo) {
            *p3 = s3f;
            *pm = m3;
        }

        p1 += st1; p2 += st2; p3 += st3; pm += st3;
        xa = nxa; xb = nxb;
    }
}

extern "C" void kernel_launch(void* const* d_in, const int* in_sizes, int n_in,
                              void* d_out, int out_size)
{
    const float* x  = (const float*)d_in[0];
    const float* W1 = (const float*)d_in[1];
    const float* b1 = (const float*)d_in[2];
    const float* W2 = (const float*)d_in[3];
    const float* b2 = (const float*)d_in[4];
    const float* W3 = (const float*)d_in[5];
    const float* b3 = (const float*)d_in[6];

    const int T = in_sizes[0] / (Bb * Ii);
    const size_t TB = (size_t)T * Bb;

    float* out      = (float*)d_out;
    float* out_mem3 = out;
    float* out_spk3 = out + TB * Oo;
    float* out_spk1 = out + 2 * TB * Oo;
    float* out_spk2 = out + 2 * TB * Oo + TB * H1;

    const int threads = Bb * 8;
    const int block   = 64;
    snn_kernel<<<threads / block, block>>>(x, W1, b1, W2, b2, W3, b3,
                                           out_mem3, out_spk3, out_spk1, out_spk2,
                                           T);
}